// round 12
// baseline (speedup 1.0000x reference)
#include <cuda_runtime.h>
#include <stdint.h>

// Shapes (fixed):
//   updates: (32, 64, 64, 128) fp32  -> 16,777,216 elems
//   mask:    same shape, int32 in [0, 2,097,152)
//   output:  (32, 128, 128, 128) fp32 -> 67,108,864 elems (256 MB)
#define N_IN        16777216
#define FLAT_OUT    2097152      // per-batch output slots (8 MB)
#define N_OUT       67108864
#define NBATCH      32
#define BLKS_PER_B  128          // chunks per batch group (1024 threads each)
#define DELAY       1            // scatter batch = zero batch - DELAY
#define NCHUNKS     ((NBATCH + DELAY) * BLKS_PER_B)   // 4224
#define PGRID       296          // persistent grid: 148 SMs x 2 CTAs

// Per-batch zero-completion counters (reset every launch by init kernel).
__device__ unsigned int g_ctr[NBATCH];

__global__ void init_ctr_kernel() {
    if (threadIdx.x < NBATCH) g_ctr[threadIdx.x] = 0u;
}

__device__ __forceinline__ unsigned int ld_acquire_gpu(const unsigned int* p) {
    unsigned int v;
    asm volatile("ld.acquire.gpu.global.u32 %0, [%1];" : "=r"(v) : "l"(p) : "memory");
    return v;
}

__device__ __forceinline__ void red_release_gpu_add(unsigned int* p, unsigned int v) {
    asm volatile("red.release.gpu.global.add.u32 [%0], %1;" :: "l"(p), "r"(v) : "memory");
}

// ---------------------------------------------------------------------------
// PERSISTENT fused zero + scatter pipeline.
//   296 resident blocks (2 per SM) loop over 4224 chunks. Chunk gc:
//     zb = gc >> 7 : zero a 64 KB chunk of batch zb's output (zb < 32)
//     sb = zb - 1  : scatter a 4096-element input chunk of batch sb after
//                    all 128 zero-chunks of batch sb have published.
//   Per-chunk body is identical to the best non-persistent kernel (R8/R11):
//   1 vec4 per thread, pure fire-and-forget RED burst, regs <= 32 so both
//   CTAs stay resident. Persistence removes ~14 wave transitions and all
//   per-block launch/drain overhead.
//   Deadlock-free: ALL blocks are resident and running. A block spinning on
//   counter[sb] waits on chunks owned by other resident blocks at earlier
//   iterations; by induction on group order (group g only ever waits on
//   g-1, and group 0 never waits) every producer makes progress.
// ---------------------------------------------------------------------------
__global__ void __launch_bounds__(1024) fused_unpool_persistent(
    const float4* __restrict__ upd,
    const int4*   __restrict__ mask,
    float*        __restrict__ out)
{
    const int t = threadIdx.x;                  // 0..1023

    for (int gc = blockIdx.x; gc < NCHUNKS; gc += PGRID) {
        const int zb = gc >> 7;                 // batch to zero
        const int c  = gc & (BLKS_PER_B - 1);   // chunk within group
        const int sb = zb - DELAY;              // batch to scatter

        const bool do_scatter = (sb >= 0) && (sb < NBATCH);

        // Prefetch scatter inputs (streaming: one-shot 128 MB input read
        // must not evict the zeroed output window from L2). In flight
        // during the zero phase below.
        float4 u = make_float4(0.f, 0.f, 0.f, 0.f);
        int4   m = make_int4(0, 0, 0, 0);
        if (do_scatter) {
            const int vi = (sb << 17) + (c << 10) + t;  // vec4 idx in batch
            u = __ldcs(&upd[vi]);
            m = __ldcs(&mask[vi]);
        }

        // ---- zero phase: 64 KB = 4096 float4, 4 per thread, coalesced ----
        if (zb < NBATCH) {
            float4* zp = reinterpret_cast<float4*>(out) +
                         ((size_t)zb << 19) + (c << 12) + t;  // FLAT_OUT/4=2^19
            const float4 z = make_float4(0.f, 0.f, 0.f, 0.f);
            zp[0]    = z;
            zp[1024] = z;
            zp[2048] = z;
            zp[3072] = z;

            __syncthreads();           // BAR.SYNC drains pending stores (HW)
            if (t == 0) red_release_gpu_add(&g_ctr[zb], 1u);  // publish
        }

        if (!do_scatter) continue;

        // ---- wait until batch sb is fully zeroed (acquire-poll) ----
        if (t == 0) {
            if (ld_acquire_gpu(&g_ctr[sb]) < BLKS_PER_B) {
                do { __nanosleep(32); }
                while (ld_acquire_gpu(&g_ctr[sb]) < BLKS_PER_B);
            }
        }
        __syncthreads();   // broadcast the acquire to the whole CTA

        // ---- scatter: 4 fire-and-forget REDs into the L2-warm window ----
        float* ob = out + ((size_t)sb << 21);               // FLAT_OUT = 2^21
        atomicAdd(ob + m.x, u.x);
        atomicAdd(ob + m.y, u.y);
        atomicAdd(ob + m.z, u.z);
        atomicAdd(ob + m.w, u.w);
    }
}

extern "C" void kernel_launch(void* const* d_in, const int* in_sizes, int n_in,
                              void* d_out, int out_size)
{
    const float4* upd  = (const float4*)d_in[0];
    const int4*   mask = (const int4*)  d_in[1];
    float*        out  = (float*)d_out;

    init_ctr_kernel<<<1, 32>>>();
    fused_unpool_persistent<<<PGRID, 1024>>>(upd, mask, out);
}

// round 13
// speedup vs baseline: 1.5748x; 1.5748x over previous
#include <cuda_runtime.h>
#include <stdint.h>

// Shapes (fixed):
//   updates: (32, 64, 64, 128) fp32  -> 16,777,216 elems
//   mask:    same shape, int32 in [0, 2,097,152)
//   output:  (32, 128, 128, 128) fp32 -> 67,108,864 elems (256 MB)
#define N_IN        16777216
#define FLAT_OUT    2097152      // per-batch output slots (8 MB)
#define N_OUT       67108864
#define NBATCH      32
#define BLKS_PER_B  128          // blocks per batch group (1024 threads each)
#define DELAY       2            // scatter batch = zero batch - DELAY

// Per-batch zero-completion counters (reset every launch by init kernel).
__device__ unsigned int g_ctr[NBATCH];

__global__ void init_ctr_kernel() {
    if (threadIdx.x < NBATCH) g_ctr[threadIdx.x] = 0u;
}

__device__ __forceinline__ unsigned int ld_acquire_gpu(const unsigned int* p) {
    unsigned int v;
    asm volatile("ld.acquire.gpu.global.u32 %0, [%1];" : "=r"(v) : "l"(p) : "memory");
    return v;
}

__device__ __forceinline__ void red_release_gpu_add(unsigned int* p, unsigned int v) {
    asm volatile("red.release.gpu.global.add.u32 [%0], %1;" :: "l"(p), "r"(v) : "memory");
}

// ---------------------------------------------------------------------------
// Fused zero + scatter pipeline — the R8 schedule (best measured: 120.9 us).
// One chunk per block; block churn + CLC backfill provide the overlap:
// a block that spins or finishes is immediately replaced by a fresh block
// that starts zeroing, so the SM always has forward-progress work.
// (Persistent CTAs and deeper per-thread work both serialized wait/scatter
// against later zero work inside a CTA and regressed — do not repeat.)
//
//   Block bid (1024 threads):
//     zb = bid >> 7 : zeroes a 64 KB chunk of batch zb's output (zb < 32)
//     sb = zb - 2   : scatters a 4096-element input chunk of batch sb after
//                     all 128 zero-blocks of batch sb have published.
//   One vec4 per thread -> the scatter is a pure fire-and-forget RED burst;
//   regs <= 32 so 2 CTAs/SM stay resident (pinned via __launch_bounds__).
//   Producers of batch sb have strictly lower block IDs (>= 256 earlier);
//   producers never spin; CTAs dispatch in bid order with backfill -> no
//   deadlock. BAR.SYNC drains the zero STGs (HW-native on B300); one
//   elected thread publishes with red.release.gpu; consumers poll with
//   ld.acquire.gpu. Scatter REDs then RMW lines still resident in L2
//   (R8 measured exactly the mandatory ~384 MB of DRAM traffic).
// ---------------------------------------------------------------------------
__global__ void __launch_bounds__(1024, 2) fused_unpool_kernel(
    const float4* __restrict__ upd,
    const int4*   __restrict__ mask,
    float*        __restrict__ out)
{
    const int bid = blockIdx.x;
    const int t   = threadIdx.x;                // 0..1023
    const int zb  = bid >> 7;                   // batch to zero
    const int c   = bid & (BLKS_PER_B - 1);     // chunk within group
    const int sb  = zb - DELAY;                 // batch to scatter

    const bool do_scatter = (sb >= 0) && (sb < NBATCH);

    // Prefetch scatter inputs (streaming / evict-first: the one-shot 128 MB
    // input read must not evict the zeroed output window from L2). These
    // LDG.128s are in flight during the zero phase below.
    float4 u = make_float4(0.f, 0.f, 0.f, 0.f);
    int4   m = make_int4(0, 0, 0, 0);
    if (do_scatter) {
        const int vi = (sb << 17) + (c << 10) + t;  // vec4 index within batch
        u = __ldcs(&upd[vi]);
        m = __ldcs(&mask[vi]);
    }

    // ---- zero phase: 64 KB = 4096 float4, 4 per thread, coalesced ----
    if (zb < NBATCH) {
        float4* zp = reinterpret_cast<float4*>(out) +
                     ((size_t)zb << 19) + (c << 12) + t;    // FLAT_OUT/4 = 2^19
        const float4 z = make_float4(0.f, 0.f, 0.f, 0.f);
        zp[0]    = z;
        zp[1024] = z;
        zp[2048] = z;
        zp[3072] = z;

        __syncthreads();               // BAR.SYNC drains pending stores (HW)
        if (t == 0) red_release_gpu_add(&g_ctr[zb], 1u);    // publish
    }

    if (!do_scatter) return;

    // ---- wait until batch sb is fully zeroed (acquire-poll, 1 thread) ----
    if (t == 0) {
        if (ld_acquire_gpu(&g_ctr[sb]) < BLKS_PER_B) {
            do { __nanosleep(32); } while (ld_acquire_gpu(&g_ctr[sb]) < BLKS_PER_B);
        }
    }
    __syncthreads();   // broadcast the acquire to the whole CTA

    // ---- scatter phase: 4 fire-and-forget REDs into the L2-warm window ----
    float* ob = out + ((size_t)sb << 21);                   // FLAT_OUT = 2^21
    atomicAdd(ob + m.x, u.x);
    atomicAdd(ob + m.y, u.y);
    atomicAdd(ob + m.z, u.z);
    atomicAdd(ob + m.w, u.w);
}

extern "C" void kernel_launch(void* const* d_in, const int* in_sizes, int n_in,
                              void* d_out, int out_size)
{
    const float4* upd  = (const float4*)d_in[0];
    const int4*   mask = (const int4*)  d_in[1];
    float*        out  = (float*)d_out;

    init_ctr_kernel<<<1, 32>>>();

    // 32 zero-groups * 128 blocks + DELAY*128 scatter-only tail blocks.
    const int grid = (NBATCH + DELAY) * BLKS_PER_B;   // 4352
    fused_unpool_kernel<<<grid, 1024>>>(upd, mask, out);
}